// round 14
// baseline (speedup 1.0000x reference)
#include <cuda_runtime.h>
#include <math.h>
#include <limits.h>

// Problem constants: b=2, nc=64, H=W=64
#define Bz 2
#define NC 64
#define Hh 64
#define Ww 64
#define Ls 4096          // H*W
#define KD 576           // nc * 3 * 3
#define EPSF 1e-7f
#define MAXC 24          // fast-path candidate capacity in k_soft
#define CQ   3           // k_corr candidate chunk per block
#define NSPLIT 6         // k_corr candidate split (768 blocks ~ residency cap)
#define RCH  12          // k_rec candidate chunk

// Scratch (worst-case cnt == Ls; actual data gives cnt ~ 12 per sample)
__device__ int   g_cnt[Bz];
__device__ int   g_list[Bz][Ls];
__device__ float g_K[Bz][Ls][KD];
__device__ float g_corr[Bz][Ls][Ls];
__device__ float g_sc[Bz][Ls][Ls];

// ---------------------------------------------------------------------------
// K1: build with in-block redundant scan (proven R13). Grid (64, Bz) x 576.
// ---------------------------------------------------------------------------
__global__ void __launch_bounds__(576) k_build(const float* __restrict__ bgin,
                                               const float* __restrict__ mask) {
    int b = blockIdx.y;
    int tid = threadIdx.x, lane = tid & 31, warp = tid >> 5;   // 18 warps

    __shared__ float sm[Ls];
    __shared__ int   s_list[Ls];
    __shared__ int   wsum[18];
    __shared__ float wred[18];

    for (int k = tid; k < Ls; k += 576) sm[k] = mask[b * Ls + k];
    __syncthreads();

    unsigned okbits = 0; int myc = 0;
    if (tid < 512) {
        #pragma unroll
        for (int j = 0; j < 8; j++) {
            int l = tid * 8 + j;
            int y = l >> 6, x = l & 63;
            int o = 1;
            #pragma unroll
            for (int dy = -1; dy <= 1; dy++) {
                int yy = y + dy;
                if (yy < 0 || yy >= Hh) continue;
                #pragma unroll
                for (int dx = -1; dx <= 1; dx++) {
                    int xx = x + dx;
                    if (xx >= 0 && xx < Ww && sm[yy * Ww + xx] != 0.0f) o = 0;
                }
            }
            okbits |= (unsigned)o << j; myc += o;
        }
    }
    int v = myc;
    #pragma unroll
    for (int off = 1; off < 32; off <<= 1) {
        int t = __shfl_up_sync(0xffffffffu, v, off);
        if (lane >= off) v += t;
    }
    if (lane == 31) wsum[warp] = v;
    __syncthreads();
    if (tid == 0) {
        int run = 0;
        #pragma unroll
        for (int w = 0; w < 18; w++) { run += wsum[w]; wsum[w] = run; }
    }
    __syncthreads();
    int excl = (v - myc) + (warp > 0 ? wsum[warp - 1] : 0);
    #pragma unroll
    for (int j = 0; j < 8; j++)
        if ((okbits >> j) & 1u) s_list[excl++] = tid * 8 + j;
    __syncthreads();
    int cnt = wsum[17];

    if (blockIdx.x == 0) {
        for (int t = tid; t < cnt; t += 576) g_list[b][t] = s_list[t];
        if (tid == 0) g_cnt[b] = cnt;
    }

    int c = tid / 9, pp = tid % 9;
    int ph = pp / 3, pw = pp % 3;
    for (int i = blockIdx.x; i < cnt; i += 64) {
        int l = s_list[i];
        int y = l >> 6, x = l & 63;
        int yy = y + ph - 1, xx = x + pw - 1;
        float v2 = 0.f;
        if (yy >= 0 && yy < Hh && xx >= 0 && xx < Ww)
            v2 = bgin[(b * NC + c) * Ls + yy * Ww + xx] * (1.f - sm[yy * Ww + xx]);
        v2 += EPSF;
        float ss = v2 * v2;
        #pragma unroll
        for (int o = 16; o > 0; o >>= 1) ss += __shfl_xor_sync(0xffffffffu, ss, o);
        if (lane == 0) wred[warp] = ss;
        __syncthreads();
        float tot = 0.f;
        #pragma unroll
        for (int w = 0; w < 18; w++) tot += wred[w];
        g_K[b][i][tid] = v2 / sqrtf(tot);
        __syncthreads();
    }
}

// ---------------------------------------------------------------------------
// K2: corr — R8 body, NSPLIT-way candidate split. Grid (64 y, NSPLIT, Bz).
// ---------------------------------------------------------------------------
__global__ void __launch_bounds__(256) k_corr(const float* __restrict__ fgin) {
    int b = blockIdx.z;
    int cnt = g_cnt[b];
    int y  = blockIdx.x;
    int iq = blockIdx.y;
    int qq = (cnt + NSPLIT - 1) / NSPLIT;
    int ibeg = iq * qq, iend = min(ibeg + qq, cnt);
    if (ibeg >= iend) return;

    int tid = threadIdx.x;
    int cgi = tid >> 4;
    int xq  = tid & 15;
    int xbase = xq * 4;

    __shared__ float sfg[32][3][68];
    __shared__ float skc[CQ][KD];
    __shared__ float buf[16][193];

    for (int i0 = ibeg; i0 < iend; i0 += CQ) {
        int nch = min(CQ, iend - i0);
        float acc[CQ][4];
        #pragma unroll
        for (int j = 0; j < CQ; j++)
            #pragma unroll
            for (int xo = 0; xo < 4; xo++) acc[j][xo] = 0.f;

        for (int t = tid; t < nch * (KD / 4); t += 256) {
            int i = t / (KD / 4), k = t % (KD / 4);
            ((float4*)skc[i])[k] = ((const float4*)&g_K[b][i0 + i][0])[k];
        }

        for (int half = 0; half < 2; half++) {
            for (int t = tid; t < 32 * 3 * 68; t += 256) {
                int ch = t / 204, rem = t % 204;
                int r = rem / 68, j = rem % 68;
                int gy = y - 1 + r;
                float v = 0.f;
                if (gy >= 0 && gy < Hh && j >= 1 && j <= 64)
                    v = fgin[(b * NC + half * 32 + ch) * Ls + gy * Ww + (j - 1)];
                sfg[ch][r][j] = v;
            }
            __syncthreads();

            #pragma unroll
            for (int c2 = 0; c2 < 2; c2++) {
                int ch = cgi * 2 + c2;
                int cglob = half * 32 + ch;
                float w[3][6];
                #pragma unroll
                for (int r = 0; r < 3; r++) {
                    float4 a = *(const float4*)&sfg[ch][r][xbase];
                    float2 e = *(const float2*)&sfg[ch][r][xbase + 4];
                    w[r][0] = a.x; w[r][1] = a.y; w[r][2] = a.z; w[r][3] = a.w;
                    w[r][4] = e.x; w[r][5] = e.y;
                }
                for (int j = 0; j < nch; j++) {
                    const float* kk = &skc[j][cglob * 9];
                    float k0 = kk[0], k1 = kk[1], k2 = kk[2];
                    float k3 = kk[3], k4 = kk[4], k5 = kk[5];
                    float k6 = kk[6], k7 = kk[7], k8 = kk[8];
                    #pragma unroll
                    for (int xo = 0; xo < 4; xo++) {
                        acc[j][xo] += k0 * w[0][xo] + k1 * w[0][xo + 1] + k2 * w[0][xo + 2]
                                    + k3 * w[1][xo] + k4 * w[1][xo + 1] + k5 * w[1][xo + 2]
                                    + k6 * w[2][xo] + k7 * w[2][xo + 1] + k8 * w[2][xo + 2];
                    }
                }
            }
            __syncthreads();
        }

        for (int j = 0; j < nch; j++)
            #pragma unroll
            for (int xo = 0; xo < 4; xo++)
                buf[cgi][j * 64 + xbase + xo] = acc[j][xo];
        __syncthreads();
        if (tid < nch * 64) {
            float s = 0.f;
            #pragma unroll
            for (int g = 0; g < 16; g++) s += buf[g][tid];
            int j = tid >> 6, x = tid & 63;
            g_corr[b][i0 + j][y * Ww + x] = s;
        }
        __syncthreads();
    }
}

// 3x3 spatial box-sum of a global corr row (zero outside grid) — slow path
__device__ __forceinline__ float boxsum_g(const float* __restrict__ row, int y, int x) {
    float a = 0.f;
    #pragma unroll
    for (int dy = -1; dy <= 1; dy++) {
        int yy = y + dy;
        if (yy < 0 || yy >= Hh) continue;
        const float* r = row + yy * Ww;
        #pragma unroll
        for (int dx = -1; dx <= 1; dx++) {
            int xx = x + dx;
            if (xx >= 0 && xx < Ww) a += r[xx];
        }
    }
    return a;
}

// ---------------------------------------------------------------------------
// K3: softmax/argmax/flow with GROUP-PARTIAL combine (exp /4). Grid (64, Bz)
// x 256 threads = 4 groups x 64 x. v values bitwise identical to R8; argmax
// winner exact (strict > within group ascending, min-index across groups).
// ---------------------------------------------------------------------------
__global__ void __launch_bounds__(256) k_soft(float* __restrict__ flowout) {
    int b = blockIdx.y, y = blockIdx.x;
    int cnt = g_cnt[b];
    int tid = threadIdx.x;
    int g = tid >> 6, x = tid & 63;
    int s = y * Ww + x;

    __shared__ float raw[MAXC][3][64];   // 18KB
    __shared__ float vsh[MAXC][64];      // 6KB (v, then e stashed in-place)
    __shared__ int   sl[MAXC];
    __shared__ float pmax[4][64];
    __shared__ float pden[4][64];
    __shared__ float pbv[4][64];
    __shared__ int   pbi[4][64];

    if (cnt <= MAXC) {
        for (int i = g; i < cnt; i += 4) {
            #pragma unroll
            for (int r = 0; r < 3; r++) {
                int gy = y - 1 + r;
                raw[i][r][x] = (gy >= 0 && gy < Hh) ? g_corr[b][i][gy * Ww + x] : 0.f;
            }
        }
        if (tid < cnt) sl[tid] = g_list[b][tid];
        __syncthreads();

        for (int i = g; i < cnt; i += 4) {
            float a = 0.f;
            #pragma unroll
            for (int r = 0; r < 3; r++) {
                #pragma unroll
                for (int dx = -1; dx <= 1; dx++) {
                    int xx = x + dx;
                    if (xx >= 0 && xx < 64) a += raw[i][r][xx];
                }
            }
            vsh[i][x] = 10.f * a;
        }
        __syncthreads();

        // pass1: group-partial vmax
        float vm = -INFINITY;
        for (int i = g; i < cnt; i += 4) vm = fmaxf(vm, vsh[i][x]);
        pmax[g][x] = vm;
        __syncthreads();
        float vmax = fmaxf(0.f,   // cnt<=MAXC<Ls: masked rows contribute v=0
                     fmaxf(fmaxf(pmax[0][x], pmax[1][x]),
                           fmaxf(pmax[2][x], pmax[3][x])));

        // pass2: group-partial denom + argmax; stash e in vsh
        float dn = 0.f; float bv = -INFINITY; int bi = INT_MAX;
        for (int i = g; i < cnt; i += 4) {
            float vv = vsh[i][x];
            float e = expf(vv - vmax);
            dn += e;
            if (vv > bv) { bv = vv; bi = i; }   // ascending in-group -> first max
            vsh[i][x] = e;
        }
        pden[g][x] = dn; pbv[g][x] = bv; pbi[g][x] = bi;
        __syncthreads();

        float denom = (float)(Ls - cnt) * expf(-vmax);
        float bestv = -INFINITY; int besti = INT_MAX;
        #pragma unroll
        for (int gg = 0; gg < 4; gg++) {
            denom += pden[gg][x];
            float v2 = pbv[gg][x]; int i2 = pbi[gg][x];
            if (v2 > bestv || (v2 == bestv && i2 < besti)) { bestv = v2; besti = i2; }
        }
        float inv = 1.f / denom;

        for (int i = g; i < cnt; i += 4)
            g_sc[b][i][s] = vsh[i][x] * inv;

        if (g == 0) {
            int lb = (besti != INT_MAX) ? sl[besti] : 0;   // cnt==0 -> 0 (matches R8)
            flowout[(b * 2 + 0) * Ls + s] = (float)(lb >> 6) - (float)y;
            flowout[(b * 2 + 1) * Ls + s] = (float)(lb & 63) - (float)x;
        }
    } else if (g == 0) {
        // generic correct fallback (unchanged)
        float vmax = (cnt < Ls) ? 0.f : -INFINITY;
        for (int i = 0; i < cnt; i++) {
            float vv = 10.f * boxsum_g(&g_corr[b][i][0], y, x);
            vmax = fmaxf(vmax, vv);
            g_sc[b][i][s] = vv;
        }
        float denom = (cnt < Ls) ? (float)(Ls - cnt) * expf(-vmax) : 0.f;
        float bestv = -INFINITY; int bestl = 0;
        for (int i = 0; i < cnt; i++) {
            float vv = g_sc[b][i][s];
            float e = expf(vv - vmax);
            denom += e;
            if (vv > bestv) { bestv = vv; bestl = g_list[b][i]; }
            g_sc[b][i][s] = e;
        }
        float inv = 1.f / denom;
        for (int i = 0; i < cnt; i++) g_sc[b][i][s] *= inv;
        flowout[(b * 2 + 0) * Ls + s] = (float)(bestl >> 6) - (float)y;
        flowout[(b * 2 + 1) * Ls + s] = (float)(bestl & 63) - (float)x;
    }
}

// ---------------------------------------------------------------------------
// K4: rec — proven R8 version. Grid (64 y, 4 cg, Bz).
// ---------------------------------------------------------------------------
__global__ void __launch_bounds__(256) k_rec(const float* __restrict__ fgin,
                                             const float* __restrict__ mask,
                                             float* __restrict__ att) {
    int b = blockIdx.z, cg = blockIdx.y, y = blockIdx.x;
    int cnt = g_cnt[b];
    int tid = threadIdx.x;
    int c16 = tid >> 4, xg = tid & 15;
    int c = cg * 16 + c16;
    int xbase = xg * 4;

    __shared__ float sk[RCH][16 * 9];
    __shared__ float ssc[RCH][3][72];
    __shared__ float smask[64];

    if (tid < 64) smask[tid] = mask[b * Ls + y * Ww + tid];
    __syncthreads();

    float acc[4] = {0.f, 0.f, 0.f, 0.f};

    for (int c0 = 0; c0 < cnt; c0 += RCH) {
        int nchunk = min(RCH, cnt - c0);
        for (int t = tid; t < nchunk * 144; t += 256) {
            int i = t / 144, k = t % 144;
            sk[i][k] = g_K[b][c0 + i][cg * 144 + k];
        }
        for (int t = tid; t < nchunk * 216; t += 256) {
            int i = t / 216, rem = t % 216;
            int r = rem / 72, j = rem % 72;
            int gy = y - 1 + r;
            float v = 0.f;
            if (gy >= 0 && gy < Hh && j >= 1 && j <= 64)
                v = g_sc[b][c0 + i][gy * Ww + (j - 1)];
            ssc[i][r][j] = v;
        }
        __syncthreads();

        for (int i = 0; i < nchunk; i++) {
            float ki[9];
            #pragma unroll
            for (int p = 0; p < 9; p++) ki[p] = sk[i][c16 * 9 + p];
            #pragma unroll
            for (int ph = 0; ph < 3; ph++) {
                const float* row = ssc[i][2 - ph];
                float4 a = *(const float4*)&row[xbase];
                float2 e = *(const float2*)&row[xbase + 4];
                float w0 = a.x, w1 = a.y, w2 = a.z, w3 = a.w, w4 = e.x, w5 = e.y;
                acc[0] += ki[ph * 3 + 0] * w2 + ki[ph * 3 + 1] * w1 + ki[ph * 3 + 2] * w0;
                acc[1] += ki[ph * 3 + 0] * w3 + ki[ph * 3 + 1] * w2 + ki[ph * 3 + 2] * w1;
                acc[2] += ki[ph * 3 + 0] * w4 + ki[ph * 3 + 1] * w3 + ki[ph * 3 + 2] * w2;
                acc[3] += ki[ph * 3 + 0] * w5 + ki[ph * 3 + 1] * w4 + ki[ph * 3 + 2] * w3;
            }
        }
        __syncthreads();
    }

    const float* fgrow = fgin + (b * NC + c) * Ls + y * Ww + xbase;
    float4 fgv = *(const float4*)fgrow;
    float4 o;
    {
        float m0 = smask[xbase + 0], m1 = smask[xbase + 1];
        float m2 = smask[xbase + 2], m3 = smask[xbase + 3];
        o.x = ((acc[0] * m0) / 9.f) * m0 + fgv.x * (1.f - m0);
        o.y = ((acc[1] * m1) / 9.f) * m1 + fgv.y * (1.f - m1);
        o.z = ((acc[2] * m2) / 9.f) * m2 + fgv.z * (1.f - m2);
        o.w = ((acc[3] * m3) / 9.f) * m3 + fgv.w * (1.f - m3);
    }
    *(float4*)(att + (b * NC + c) * Ls + y * Ww + xbase) = o;
}

// ---------------------------------------------------------------------------
extern "C" void kernel_launch(void* const* d_in, const int* in_sizes, int n_in,
                              void* d_out, int out_size) {
    const float* fg   = (const float*)d_in[0];   // foreground [2,64,64,64]
    const float* bg   = (const float*)d_in[1];   // background [2,64,64,64]
    const float* mask = (const float*)d_in[2];   // mask       [2,1,64,64]
    float* att  = (float*)d_out;                 // attended   [2,64,64,64]
    float* flow = (float*)d_out + Bz * NC * Ls;  // flow       [2,2,64,64]

    k_build<<<dim3(64, Bz), 576>>>(bg, mask);
    k_corr<<<dim3(64, NSPLIT, Bz), 256>>>(fg);
    k_soft<<<dim3(64, Bz), 256>>>(flow);
    k_rec<<<dim3(64, 4, Bz), 256>>>(fg, mask, att);
}

// round 15
// speedup vs baseline: 1.0235x; 1.0235x over previous
#include <cuda_runtime.h>
#include <math.h>

// Problem constants: b=2, nc=64, H=W=64
#define Bz 2
#define NC 64
#define Hh 64
#define Ww 64
#define Ls 4096          // H*W
#define KD 576           // nc * 3 * 3
#define EPSF 1e-7f
#define MAXC 24          // fast-path candidate capacity in k_soft
#define CQ   3           // k_corr candidate chunk per block
#define RCH  12          // k_rec candidate chunk

// Scratch (worst-case cnt == Ls; actual data gives cnt ~ 12 per sample)
__device__ int   g_cnt[Bz];
__device__ int   g_list[Bz][Ls];
__device__ float g_K[Bz][Ls][KD];
__device__ float g_corr[Bz][Ls][Ls];
__device__ float g_sc[Bz][Ls][Ls];

// ---------------------------------------------------------------------------
// K1: build with in-block redundant scan (proven R13). Grid (64, Bz) x 576.
// ---------------------------------------------------------------------------
__global__ void __launch_bounds__(576) k_build(const float* __restrict__ bgin,
                                               const float* __restrict__ mask) {
    int b = blockIdx.y;
    int tid = threadIdx.x, lane = tid & 31, warp = tid >> 5;   // 18 warps

    __shared__ float sm[Ls];
    __shared__ int   s_list[Ls];
    __shared__ int   wsum[18];
    __shared__ float wred[18];

    for (int k = tid; k < Ls; k += 576) sm[k] = mask[b * Ls + k];
    __syncthreads();

    unsigned okbits = 0; int myc = 0;
    if (tid < 512) {
        #pragma unroll
        for (int j = 0; j < 8; j++) {
            int l = tid * 8 + j;
            int y = l >> 6, x = l & 63;
            int o = 1;
            #pragma unroll
            for (int dy = -1; dy <= 1; dy++) {
                int yy = y + dy;
                if (yy < 0 || yy >= Hh) continue;
                #pragma unroll
                for (int dx = -1; dx <= 1; dx++) {
                    int xx = x + dx;
                    if (xx >= 0 && xx < Ww && sm[yy * Ww + xx] != 0.0f) o = 0;
                }
            }
            okbits |= (unsigned)o << j; myc += o;
        }
    }
    int v = myc;
    #pragma unroll
    for (int off = 1; off < 32; off <<= 1) {
        int t = __shfl_up_sync(0xffffffffu, v, off);
        if (lane >= off) v += t;
    }
    if (lane == 31) wsum[warp] = v;
    __syncthreads();
    if (tid == 0) {
        int run = 0;
        #pragma unroll
        for (int w = 0; w < 18; w++) { run += wsum[w]; wsum[w] = run; }
    }
    __syncthreads();
    int excl = (v - myc) + (warp > 0 ? wsum[warp - 1] : 0);
    #pragma unroll
    for (int j = 0; j < 8; j++)
        if ((okbits >> j) & 1u) s_list[excl++] = tid * 8 + j;
    __syncthreads();
    int cnt = wsum[17];

    if (blockIdx.x == 0) {
        for (int t = tid; t < cnt; t += 576) g_list[b][t] = s_list[t];
        if (tid == 0) g_cnt[b] = cnt;
    }

    int c = tid / 9, pp = tid % 9;
    int ph = pp / 3, pw = pp % 3;
    for (int i = blockIdx.x; i < cnt; i += 64) {
        int l = s_list[i];
        int y = l >> 6, x = l & 63;
        int yy = y + ph - 1, xx = x + pw - 1;
        float v2 = 0.f;
        if (yy >= 0 && yy < Hh && xx >= 0 && xx < Ww)
            v2 = bgin[(b * NC + c) * Ls + yy * Ww + xx] * (1.f - sm[yy * Ww + xx]);
        v2 += EPSF;
        float ss = v2 * v2;
        #pragma unroll
        for (int o = 16; o > 0; o >>= 1) ss += __shfl_xor_sync(0xffffffffu, ss, o);
        if (lane == 0) wred[warp] = ss;
        __syncthreads();
        float tot = 0.f;
        #pragma unroll
        for (int w = 0; w < 18; w++) tot += wred[w];
        g_K[b][i][tid] = v2 / sqrtf(tot);
        __syncthreads();
    }
}

// ---------------------------------------------------------------------------
// K2: corr — proven R8 version. Grid (64 y, 4 cand-quarter, Bz).
// ---------------------------------------------------------------------------
__global__ void __launch_bounds__(256) k_corr(const float* __restrict__ fgin) {
    int b = blockIdx.z;
    int cnt = g_cnt[b];
    int y  = blockIdx.x;
    int iq = blockIdx.y;
    int qq = (cnt + 3) >> 2;
    int ibeg = iq * qq, iend = min(ibeg + qq, cnt);
    if (ibeg >= iend) return;

    int tid = threadIdx.x;
    int cgi = tid >> 4;
    int xq  = tid & 15;
    int xbase = xq * 4;

    __shared__ float sfg[32][3][68];
    __shared__ float skc[CQ][KD];
    __shared__ float buf[16][193];

    for (int i0 = ibeg; i0 < iend; i0 += CQ) {
        int nch = min(CQ, iend - i0);
        float acc[CQ][4];
        #pragma unroll
        for (int j = 0; j < CQ; j++)
            #pragma unroll
            for (int xo = 0; xo < 4; xo++) acc[j][xo] = 0.f;

        for (int t = tid; t < nch * (KD / 4); t += 256) {
            int i = t / (KD / 4), k = t % (KD / 4);
            ((float4*)skc[i])[k] = ((const float4*)&g_K[b][i0 + i][0])[k];
        }

        for (int half = 0; half < 2; half++) {
            for (int t = tid; t < 32 * 3 * 68; t += 256) {
                int ch = t / 204, rem = t % 204;
                int r = rem / 68, j = rem % 68;
                int gy = y - 1 + r;
                float v = 0.f;
                if (gy >= 0 && gy < Hh && j >= 1 && j <= 64)
                    v = fgin[(b * NC + half * 32 + ch) * Ls + gy * Ww + (j - 1)];
                sfg[ch][r][j] = v;
            }
            __syncthreads();

            #pragma unroll
            for (int c2 = 0; c2 < 2; c2++) {
                int ch = cgi * 2 + c2;
                int cglob = half * 32 + ch;
                float w[3][6];
                #pragma unroll
                for (int r = 0; r < 3; r++) {
                    float4 a = *(const float4*)&sfg[ch][r][xbase];
                    float2 e = *(const float2*)&sfg[ch][r][xbase + 4];
                    w[r][0] = a.x; w[r][1] = a.y; w[r][2] = a.z; w[r][3] = a.w;
                    w[r][4] = e.x; w[r][5] = e.y;
                }
                for (int j = 0; j < nch; j++) {
                    const float* kk = &skc[j][cglob * 9];
                    float k0 = kk[0], k1 = kk[1], k2 = kk[2];
                    float k3 = kk[3], k4 = kk[4], k5 = kk[5];
                    float k6 = kk[6], k7 = kk[7], k8 = kk[8];
                    #pragma unroll
                    for (int xo = 0; xo < 4; xo++) {
                        acc[j][xo] += k0 * w[0][xo] + k1 * w[0][xo + 1] + k2 * w[0][xo + 2]
                                    + k3 * w[1][xo] + k4 * w[1][xo + 1] + k5 * w[1][xo + 2]
                                    + k6 * w[2][xo] + k7 * w[2][xo + 1] + k8 * w[2][xo + 2];
                    }
                }
            }
            __syncthreads();
        }

        for (int j = 0; j < nch; j++)
            #pragma unroll
            for (int xo = 0; xo < 4; xo++)
                buf[cgi][j * 64 + xbase + xo] = acc[j][xo];
        __syncthreads();
        if (tid < nch * 64) {
            float s = 0.f;
            #pragma unroll
            for (int g = 0; g < 16; g++) s += buf[g][tid];
            int j = tid >> 6, x = tid & 63;
            g_corr[b][i0 + j][y * Ww + x] = s;
        }
        __syncthreads();
    }
}

// 3x3 spatial box-sum of a global corr row (zero outside grid) — slow path
__device__ __forceinline__ float boxsum_g(const float* __restrict__ row, int y, int x) {
    float a = 0.f;
    #pragma unroll
    for (int dy = -1; dy <= 1; dy++) {
        int yy = y + dy;
        if (yy < 0 || yy >= Hh) continue;
        const float* r = row + yy * Ww;
        #pragma unroll
        for (int dx = -1; dx <= 1; dx++) {
            int xx = x + dx;
            if (xx >= 0 && xx < Ww) a += r[xx];
        }
    }
    return a;
}

// ---------------------------------------------------------------------------
// K3: softmax/argmax/flow — proven R8 v2. Grid (64 y, Bz) x 256 threads.
// ---------------------------------------------------------------------------
__global__ void __launch_bounds__(256) k_soft(float* __restrict__ flowout) {
    int b = blockIdx.y, y = blockIdx.x;
    int cnt = g_cnt[b];
    int tid = threadIdx.x;
    int g = tid >> 6, x = tid & 63;
    int s = y * Ww + x;

    __shared__ float raw[MAXC][3][64];
    __shared__ float vsh[MAXC][64];
    __shared__ int   sl[MAXC];

    if (cnt <= MAXC) {
        for (int i = g; i < cnt; i += 4) {
            #pragma unroll
            for (int r = 0; r < 3; r++) {
                int gy = y - 1 + r;
                raw[i][r][x] = (gy >= 0 && gy < Hh) ? g_corr[b][i][gy * Ww + x] : 0.f;
            }
        }
        if (tid < cnt) sl[tid] = g_list[b][tid];
        __syncthreads();

        for (int i = g; i < cnt; i += 4) {
            float a = 0.f;
            #pragma unroll
            for (int r = 0; r < 3; r++) {
                #pragma unroll
                for (int dx = -1; dx <= 1; dx++) {
                    int xx = x + dx;
                    if (xx >= 0 && xx < 64) a += raw[i][r][xx];
                }
            }
            vsh[i][x] = 10.f * a;
        }
        __syncthreads();

        float vmax = (cnt < Ls) ? 0.f : -INFINITY;
        for (int i = 0; i < cnt; i++) vmax = fmaxf(vmax, vsh[i][x]);
        float denom = (cnt < Ls) ? (float)(Ls - cnt) * expf(-vmax) : 0.f;
        float bestv = -INFINITY; int bestl = 0;
        for (int i = 0; i < cnt; i++) {
            float vv = vsh[i][x];
            denom += expf(vv - vmax);
            if (vv > bestv) { bestv = vv; bestl = sl[i]; }   // ascending -> first max
        }
        float inv = 1.f / denom;
        for (int i = g; i < cnt; i += 4)
            g_sc[b][i][s] = expf(vsh[i][x] - vmax) * inv;

        if (g == 0) {
            flowout[(b * 2 + 0) * Ls + s] = (float)(bestl >> 6) - (float)y;
            flowout[(b * 2 + 1) * Ls + s] = (float)(bestl & 63) - (float)x;
        }
    } else if (g == 0) {
        float vmax = (cnt < Ls) ? 0.f : -INFINITY;
        for (int i = 0; i < cnt; i++) {
            float vv = 10.f * boxsum_g(&g_corr[b][i][0], y, x);
            vmax = fmaxf(vmax, vv);
            g_sc[b][i][s] = vv;
        }
        float denom = (cnt < Ls) ? (float)(Ls - cnt) * expf(-vmax) : 0.f;
        float bestv = -INFINITY; int bestl = 0;
        for (int i = 0; i < cnt; i++) {
            float vv = g_sc[b][i][s];
            float e = expf(vv - vmax);
            denom += e;
            if (vv > bestv) { bestv = vv; bestl = g_list[b][i]; }
            g_sc[b][i][s] = e;
        }
        float inv = 1.f / denom;
        for (int i = 0; i < cnt; i++) g_sc[b][i][s] *= inv;
        flowout[(b * 2 + 0) * Ls + s] = (float)(bestl >> 6) - (float)y;
        flowout[(b * 2 + 1) * Ls + s] = (float)(bestl & 63) - (float)x;
    }
}

// ---------------------------------------------------------------------------
// K4: rec — 8-way channel split. Grid (64 y, 8 cg, Bz) = 1024 blocks.
// Thread = (c8 in 8, xg in 32): 2 outputs each, float2 window loads.
// Per-output accumulation order bitwise identical to the proven R8 body.
// ---------------------------------------------------------------------------
__global__ void __launch_bounds__(256) k_rec(const float* __restrict__ fgin,
                                             const float* __restrict__ mask,
                                             float* __restrict__ att) {
    int b = blockIdx.z, cg = blockIdx.y, y = blockIdx.x;   // cg 0..7
    int cnt = g_cnt[b];
    int tid = threadIdx.x;
    int c8 = tid >> 5, xg = tid & 31;
    int c = cg * 8 + c8;
    int xbase = xg * 2;

    __shared__ __align__(16) float sk[RCH][8 * 9];    // 3.4KB (this cg's 8-channel slice)
    __shared__ __align__(16) float ssc[RCH][3][72];   // 10.1KB; col j holds score x = j-1
    __shared__ float smask[64];

    if (tid < 64) smask[tid] = mask[b * Ls + y * Ww + tid];
    __syncthreads();

    float acc[2] = {0.f, 0.f};

    for (int c0 = 0; c0 < cnt; c0 += RCH) {
        int nchunk = min(RCH, cnt - c0);
        for (int t = tid; t < nchunk * 72; t += 256) {
            int i = t / 72, k = t % 72;
            sk[i][k] = g_K[b][c0 + i][cg * 72 + k];
        }
        for (int t = tid; t < nchunk * 216; t += 256) {
            int i = t / 216, rem = t % 216;
            int r = rem / 72, j = rem % 72;
            int gy = y - 1 + r;
            float v = 0.f;
            if (gy >= 0 && gy < Hh && j >= 1 && j <= 64)
                v = g_sc[b][c0 + i][gy * Ww + (j - 1)];
            ssc[i][r][j] = v;
        }
        __syncthreads();

        for (int i = 0; i < nchunk; i++) {
            float ki[9];
            #pragma unroll
            for (int p = 0; p < 9; p++) ki[p] = sk[i][c8 * 9 + p];   // broadcast
            #pragma unroll
            for (int ph = 0; ph < 3; ph++) {
                const float* row = ssc[i][2 - ph];                   // yy = y+1-ph
                float2 a = *(const float2*)&row[xbase];              // 8B aligned
                float2 e = *(const float2*)&row[xbase + 2];
                float w0 = a.x, w1 = a.y, w2 = e.x, w3 = e.y;
                // score col j = x+2-pw (col j holds x=j-1); same 3-term order as R8
                acc[0] += ki[ph * 3 + 0] * w2 + ki[ph * 3 + 1] * w1 + ki[ph * 3 + 2] * w0;
                acc[1] += ki[ph * 3 + 0] * w3 + ki[ph * 3 + 1] * w2 + ki[ph * 3 + 2] * w1;
            }
        }
        __syncthreads();
    }

    const float* fgrow = fgin + (b * NC + c) * Ls + y * Ww + xbase;
    float2 fgv = *(const float2*)fgrow;
    float2 o;
    {
        float m0 = smask[xbase + 0], m1 = smask[xbase + 1];
        o.x = ((acc[0] * m0) / 9.f) * m0 + fgv.x * (1.f - m0);
        o.y = ((acc[1] * m1) / 9.f) * m1 + fgv.y * (1.f - m1);
    }
    *(float2*)(att + (b * NC + c) * Ls + y * Ww + xbase) = o;
}

// ---------------------------------------------------------------------------
extern "C" void kernel_launch(void* const* d_in, const int* in_sizes, int n_in,
                              void* d_out, int out_size) {
    const float* fg   = (const float*)d_in[0];   // foreground [2,64,64,64]
    const float* bg   = (const float*)d_in[1];   // background [2,64,64,64]
    const float* mask = (const float*)d_in[2];   // mask       [2,1,64,64]
    float* att  = (float*)d_out;                 // attended   [2,64,64,64]
    float* flow = (float*)d_out + Bz * NC * Ls;  // flow       [2,2,64,64]

    k_build<<<dim3(64, Bz), 576>>>(bg, mask);
    k_corr<<<dim3(64, 4, Bz), 256>>>(fg);
    k_soft<<<dim3(64, Bz), 256>>>(flow);
    k_rec<<<dim3(64, 8, Bz), 256>>>(fg, mask, att);
}

// round 16
// speedup vs baseline: 1.0543x; 1.0300x over previous
#include <cuda_runtime.h>
#include <math.h>

// Problem constants: b=2, nc=64, H=W=64
#define Bz 2
#define NC 64
#define Hh 64
#define Ww 64
#define Ls 4096          // H*W
#define KD 576           // nc * 3 * 3
#define EPSF 1e-7f
#define MAXC 24          // fast-path candidate capacity in k_soft
#define CQ   3           // k_corr candidate chunk per block
#define RCH  12          // k_rec candidate chunk

// Scratch (worst-case cnt == Ls; actual data gives cnt ~ 12 per sample)
__device__ int   g_cnt[Bz];
__device__ int   g_list[Bz][Ls];
__device__ float g_K[Bz][Ls][KD];
__device__ float g_corr[Bz][Ls][Ls];
__device__ float g_sc[Bz][Ls][Ls];

// ---------------------------------------------------------------------------
// K1: build with in-block redundant scan (proven R13). Grid (64, Bz) x 576.
// ---------------------------------------------------------------------------
__global__ void __launch_bounds__(576) k_build(const float* __restrict__ bgin,
                                               const float* __restrict__ mask) {
    int b = blockIdx.y;
    int tid = threadIdx.x, lane = tid & 31, warp = tid >> 5;   // 18 warps

    __shared__ float sm[Ls];
    __shared__ int   s_list[Ls];
    __shared__ int   wsum[18];
    __shared__ float wred[18];

    for (int k = tid; k < Ls; k += 576) sm[k] = mask[b * Ls + k];
    __syncthreads();

    unsigned okbits = 0; int myc = 0;
    if (tid < 512) {
        #pragma unroll
        for (int j = 0; j < 8; j++) {
            int l = tid * 8 + j;
            int y = l >> 6, x = l & 63;
            int o = 1;
            #pragma unroll
            for (int dy = -1; dy <= 1; dy++) {
                int yy = y + dy;
                if (yy < 0 || yy >= Hh) continue;
                #pragma unroll
                for (int dx = -1; dx <= 1; dx++) {
                    int xx = x + dx;
                    if (xx >= 0 && xx < Ww && sm[yy * Ww + xx] != 0.0f) o = 0;
                }
            }
            okbits |= (unsigned)o << j; myc += o;
        }
    }
    int v = myc;
    #pragma unroll
    for (int off = 1; off < 32; off <<= 1) {
        int t = __shfl_up_sync(0xffffffffu, v, off);
        if (lane >= off) v += t;
    }
    if (lane == 31) wsum[warp] = v;
    __syncthreads();
    if (tid == 0) {
        int run = 0;
        #pragma unroll
        for (int w = 0; w < 18; w++) { run += wsum[w]; wsum[w] = run; }
    }
    __syncthreads();
    int excl = (v - myc) + (warp > 0 ? wsum[warp - 1] : 0);
    #pragma unroll
    for (int j = 0; j < 8; j++)
        if ((okbits >> j) & 1u) s_list[excl++] = tid * 8 + j;
    __syncthreads();
    int cnt = wsum[17];

    if (blockIdx.x == 0) {
        for (int t = tid; t < cnt; t += 576) g_list[b][t] = s_list[t];
        if (tid == 0) g_cnt[b] = cnt;
    }

    int c = tid / 9, pp = tid % 9;
    int ph = pp / 3, pw = pp % 3;
    for (int i = blockIdx.x; i < cnt; i += 64) {
        int l = s_list[i];
        int y = l >> 6, x = l & 63;
        int yy = y + ph - 1, xx = x + pw - 1;
        float v2 = 0.f;
        if (yy >= 0 && yy < Hh && xx >= 0 && xx < Ww)
            v2 = bgin[(b * NC + c) * Ls + yy * Ww + xx] * (1.f - sm[yy * Ww + xx]);
        v2 += EPSF;
        float ss = v2 * v2;
        #pragma unroll
        for (int o = 16; o > 0; o >>= 1) ss += __shfl_xor_sync(0xffffffffu, ss, o);
        if (lane == 0) wred[warp] = ss;
        __syncthreads();
        float tot = 0.f;
        #pragma unroll
        for (int w = 0; w < 18; w++) tot += wred[w];
        g_K[b][i][tid] = v2 / sqrtf(tot);
        __syncthreads();
    }
}

// ---------------------------------------------------------------------------
// K2: corr — proven R8 version. Grid (64 y, 4 cand-quarter, Bz).
// ---------------------------------------------------------------------------
__global__ void __launch_bounds__(256) k_corr(const float* __restrict__ fgin) {
    int b = blockIdx.z;
    int cnt = g_cnt[b];
    int y  = blockIdx.x;
    int iq = blockIdx.y;
    int qq = (cnt + 3) >> 2;
    int ibeg = iq * qq, iend = min(ibeg + qq, cnt);
    if (ibeg >= iend) return;

    int tid = threadIdx.x;
    int cgi = tid >> 4;
    int xq  = tid & 15;
    int xbase = xq * 4;

    __shared__ float sfg[32][3][68];
    __shared__ float skc[CQ][KD];
    __shared__ float buf[16][193];

    for (int i0 = ibeg; i0 < iend; i0 += CQ) {
        int nch = min(CQ, iend - i0);
        float acc[CQ][4];
        #pragma unroll
        for (int j = 0; j < CQ; j++)
            #pragma unroll
            for (int xo = 0; xo < 4; xo++) acc[j][xo] = 0.f;

        for (int t = tid; t < nch * (KD / 4); t += 256) {
            int i = t / (KD / 4), k = t % (KD / 4);
            ((float4*)skc[i])[k] = ((const float4*)&g_K[b][i0 + i][0])[k];
        }

        for (int half = 0; half < 2; half++) {
            for (int t = tid; t < 32 * 3 * 68; t += 256) {
                int ch = t / 204, rem = t % 204;
                int r = rem / 68, j = rem % 68;
                int gy = y - 1 + r;
                float v = 0.f;
                if (gy >= 0 && gy < Hh && j >= 1 && j <= 64)
                    v = fgin[(b * NC + half * 32 + ch) * Ls + gy * Ww + (j - 1)];
                sfg[ch][r][j] = v;
            }
            __syncthreads();

            #pragma unroll
            for (int c2 = 0; c2 < 2; c2++) {
                int ch = cgi * 2 + c2;
                int cglob = half * 32 + ch;
                float w[3][6];
                #pragma unroll
                for (int r = 0; r < 3; r++) {
                    float4 a = *(const float4*)&sfg[ch][r][xbase];
                    float2 e = *(const float2*)&sfg[ch][r][xbase + 4];
                    w[r][0] = a.x; w[r][1] = a.y; w[r][2] = a.z; w[r][3] = a.w;
                    w[r][4] = e.x; w[r][5] = e.y;
                }
                for (int j = 0; j < nch; j++) {
                    const float* kk = &skc[j][cglob * 9];
                    float k0 = kk[0], k1 = kk[1], k2 = kk[2];
                    float k3 = kk[3], k4 = kk[4], k5 = kk[5];
                    float k6 = kk[6], k7 = kk[7], k8 = kk[8];
                    #pragma unroll
                    for (int xo = 0; xo < 4; xo++) {
                        acc[j][xo] += k0 * w[0][xo] + k1 * w[0][xo + 1] + k2 * w[0][xo + 2]
                                    + k3 * w[1][xo] + k4 * w[1][xo + 1] + k5 * w[1][xo + 2]
                                    + k6 * w[2][xo] + k7 * w[2][xo + 1] + k8 * w[2][xo + 2];
                    }
                }
            }
            __syncthreads();
        }

        for (int j = 0; j < nch; j++)
            #pragma unroll
            for (int xo = 0; xo < 4; xo++)
                buf[cgi][j * 64 + xbase + xo] = acc[j][xo];
        __syncthreads();
        if (tid < nch * 64) {
            float s = 0.f;
            #pragma unroll
            for (int g = 0; g < 16; g++) s += buf[g][tid];
            int j = tid >> 6, x = tid & 63;
            g_corr[b][i0 + j][y * Ww + x] = s;
        }
        __syncthreads();
    }
}

// 3x3 spatial box-sum of a global corr row (zero outside grid) — slow path
__device__ __forceinline__ float boxsum_g(const float* __restrict__ row, int y, int x) {
    float a = 0.f;
    #pragma unroll
    for (int dy = -1; dy <= 1; dy++) {
        int yy = y + dy;
        if (yy < 0 || yy >= Hh) continue;
        const float* r = row + yy * Ww;
        #pragma unroll
        for (int dx = -1; dx <= 1; dx++) {
            int xx = x + dx;
            if (xx >= 0 && xx < Ww) a += r[xx];
        }
    }
    return a;
}

// ---------------------------------------------------------------------------
// K3: softmax/argmax/flow — proven R8 v2. Grid (64 y, Bz) x 256 threads.
// ---------------------------------------------------------------------------
__global__ void __launch_bounds__(256) k_soft(float* __restrict__ flowout) {
    int b = blockIdx.y, y = blockIdx.x;
    int cnt = g_cnt[b];
    int tid = threadIdx.x;
    int g = tid >> 6, x = tid & 63;
    int s = y * Ww + x;

    __shared__ float raw[MAXC][3][64];
    __shared__ float vsh[MAXC][64];
    __shared__ int   sl[MAXC];

    if (cnt <= MAXC) {
        for (int i = g; i < cnt; i += 4) {
            #pragma unroll
            for (int r = 0; r < 3; r++) {
                int gy = y - 1 + r;
                raw[i][r][x] = (gy >= 0 && gy < Hh) ? g_corr[b][i][gy * Ww + x] : 0.f;
            }
        }
        if (tid < cnt) sl[tid] = g_list[b][tid];
        __syncthreads();

        for (int i = g; i < cnt; i += 4) {
            float a = 0.f;
            #pragma unroll
            for (int r = 0; r < 3; r++) {
                #pragma unroll
                for (int dx = -1; dx <= 1; dx++) {
                    int xx = x + dx;
                    if (xx >= 0 && xx < 64) a += raw[i][r][xx];
                }
            }
            vsh[i][x] = 10.f * a;
        }
        __syncthreads();

        float vmax = (cnt < Ls) ? 0.f : -INFINITY;
        for (int i = 0; i < cnt; i++) vmax = fmaxf(vmax, vsh[i][x]);
        float denom = (cnt < Ls) ? (float)(Ls - cnt) * expf(-vmax) : 0.f;
        float bestv = -INFINITY; int bestl = 0;
        for (int i = 0; i < cnt; i++) {
            float vv = vsh[i][x];
            denom += expf(vv - vmax);
            if (vv > bestv) { bestv = vv; bestl = sl[i]; }   // ascending -> first max
        }
        float inv = 1.f / denom;
        for (int i = g; i < cnt; i += 4)
            g_sc[b][i][s] = expf(vsh[i][x] - vmax) * inv;

        if (g == 0) {
            flowout[(b * 2 + 0) * Ls + s] = (float)(bestl >> 6) - (float)y;
            flowout[(b * 2 + 1) * Ls + s] = (float)(bestl & 63) - (float)x;
        }
    } else if (g == 0) {
        float vmax = (cnt < Ls) ? 0.f : -INFINITY;
        for (int i = 0; i < cnt; i++) {
            float vv = 10.f * boxsum_g(&g_corr[b][i][0], y, x);
            vmax = fmaxf(vmax, vv);
            g_sc[b][i][s] = vv;
        }
        float denom = (cnt < Ls) ? (float)(Ls - cnt) * expf(-vmax) : 0.f;
        float bestv = -INFINITY; int bestl = 0;
        for (int i = 0; i < cnt; i++) {
            float vv = g_sc[b][i][s];
            float e = expf(vv - vmax);
            denom += e;
            if (vv > bestv) { bestv = vv; bestl = g_list[b][i]; }
            g_sc[b][i][s] = e;
        }
        float inv = 1.f / denom;
        for (int i = 0; i < cnt; i++) g_sc[b][i][s] *= inv;
        flowout[(b * 2 + 0) * Ls + s] = (float)(bestl >> 6) - (float)y;
        flowout[(b * 2 + 1) * Ls + s] = (float)(bestl & 63) - (float)x;
    }
}

// ---------------------------------------------------------------------------
// K4: rec — proven R8 version (4-way cg split), sk staging vectorized.
// Grid (64 y, 4 cg, Bz).
// ---------------------------------------------------------------------------
__global__ void __launch_bounds__(256) k_rec(const float* __restrict__ fgin,
                                             const float* __restrict__ mask,
                                             float* __restrict__ att) {
    int b = blockIdx.z, cg = blockIdx.y, y = blockIdx.x;
    int cnt = g_cnt[b];
    int tid = threadIdx.x;
    int c16 = tid >> 4, xg = tid & 15;
    int c = cg * 16 + c16;
    int xbase = xg * 4;

    __shared__ __align__(16) float sk[RCH][16 * 9];   // rows 576B: float4-clean
    __shared__ float ssc[RCH][3][72];
    __shared__ float smask[64];

    if (tid < 64) smask[tid] = mask[b * Ls + y * Ww + tid];
    __syncthreads();

    float acc[4] = {0.f, 0.f, 0.f, 0.f};

    for (int c0 = 0; c0 < cnt; c0 += RCH) {
        int nchunk = min(RCH, cnt - c0);
        // sk staging as float4 copies (src offset cg*144 floats = 576B aligned)
        for (int t = tid; t < nchunk * 36; t += 256) {
            int i = t / 36, k = t % 36;
            ((float4*)sk[i])[k] = ((const float4*)&g_K[b][c0 + i][cg * 144])[k];
        }
        for (int t = tid; t < nchunk * 216; t += 256) {
            int i = t / 216, rem = t % 216;
            int r = rem / 72, j = rem % 72;
            int gy = y - 1 + r;
            float v = 0.f;
            if (gy >= 0 && gy < Hh && j >= 1 && j <= 64)
                v = g_sc[b][c0 + i][gy * Ww + (j - 1)];
            ssc[i][r][j] = v;
        }
        __syncthreads();

        for (int i = 0; i < nchunk; i++) {
            float ki[9];
            #pragma unroll
            for (int p = 0; p < 9; p++) ki[p] = sk[i][c16 * 9 + p];
            #pragma unroll
            for (int ph = 0; ph < 3; ph++) {
                const float* row = ssc[i][2 - ph];
                float4 a = *(const float4*)&row[xbase];
                float2 e = *(const float2*)&row[xbase + 4];
                float w0 = a.x, w1 = a.y, w2 = a.z, w3 = a.w, w4 = e.x, w5 = e.y;
                acc[0] += ki[ph * 3 + 0] * w2 + ki[ph * 3 + 1] * w1 + ki[ph * 3 + 2] * w0;
                acc[1] += ki[ph * 3 + 0] * w3 + ki[ph * 3 + 1] * w2 + ki[ph * 3 + 2] * w1;
                acc[2] += ki[ph * 3 + 0] * w4 + ki[ph * 3 + 1] * w3 + ki[ph * 3 + 2] * w2;
                acc[3] += ki[ph * 3 + 0] * w5 + ki[ph * 3 + 1] * w4 + ki[ph * 3 + 2] * w3;
            }
        }
        __syncthreads();
    }

    const float* fgrow = fgin + (b * NC + c) * Ls + y * Ww + xbase;
    float4 fgv = *(const float4*)fgrow;
    float4 o;
    {
        float m0 = smask[xbase + 0], m1 = smask[xbase + 1];
        float m2 = smask[xbase + 2], m3 = smask[xbase + 3];
        o.x = ((acc[0] * m0) / 9.f) * m0 + fgv.x * (1.f - m0);
        o.y = ((acc[1] * m1) / 9.f) * m1 + fgv.y * (1.f - m1);
        o.z = ((acc[2] * m2) / 9.f) * m2 + fgv.z * (1.f - m2);
        o.w = ((acc[3] * m3) / 9.f) * m3 + fgv.w * (1.f - m3);
    }
    *(float4*)(att + (b * NC + c) * Ls + y * Ww + xbase) = o;
}

// ---------------------------------------------------------------------------
extern "C" void kernel_launch(void* const* d_in, const int* in_sizes, int n_in,
                              void* d_out, int out_size) {
    const float* fg   = (const float*)d_in[0];   // foreground [2,64,64,64]
    const float* bg   = (const float*)d_in[1];   // background [2,64,64,64]
    const float* mask = (const float*)d_in[2];   // mask       [2,1,64,64]
    float* att  = (float*)d_out;                 // attended   [2,64,64,64]
    float* flow = (float*)d_out + Bz * NC * Ls;  // flow       [2,2,64,64]

    k_build<<<dim3(64, Bz), 576>>>(bg, mask);
    k_corr<<<dim3(64, 4, Bz), 256>>>(fg);
    k_soft<<<dim3(64, Bz), 256>>>(flow);
    k_rec<<<dim3(64, 4, Bz), 256>>>(fg, mask, att);
}

// round 17
// speedup vs baseline: 1.0831x; 1.0274x over previous
#include <cuda_runtime.h>
#include <math.h>

// Problem constants: b=2, nc=64, H=W=64
#define Bz 2
#define NC 64
#define Hh 64
#define Ww 64
#define Ls 4096          // H*W
#define KD 576           // nc * 3 * 3
#define EPSF 1e-7f
#define MAXC 24          // fast-path candidate capacity in k_soft
#define CQ   3           // k_corr candidate chunk per block
#define RCH  12          // k_rec candidate chunk

// Scratch (worst-case cnt == Ls; actual data gives cnt ~ 12 per sample)
__device__ int   g_cnt[Bz];
__device__ int   g_list[Bz][Ls];
__device__ float g_K[Bz][Ls][KD];
__device__ float g_corr[Bz][Ls][Ls];
__device__ float g_sc[Bz][Ls][Ls];

// ---------------------------------------------------------------------------
// K1: build with in-block redundant scan (proven R13). Grid (64, Bz) x 576.
// ---------------------------------------------------------------------------
__global__ void __launch_bounds__(576) k_build(const float* __restrict__ bgin,
                                               const float* __restrict__ mask) {
    int b = blockIdx.y;
    int tid = threadIdx.x, lane = tid & 31, warp = tid >> 5;   // 18 warps

    __shared__ float sm[Ls];
    __shared__ int   s_list[Ls];
    __shared__ int   wsum[18];
    __shared__ float wred[18];

    for (int k = tid; k < Ls; k += 576) sm[k] = mask[b * Ls + k];
    __syncthreads();

    unsigned okbits = 0; int myc = 0;
    if (tid < 512) {
        #pragma unroll
        for (int j = 0; j < 8; j++) {
            int l = tid * 8 + j;
            int y = l >> 6, x = l & 63;
            int o = 1;
            #pragma unroll
            for (int dy = -1; dy <= 1; dy++) {
                int yy = y + dy;
                if (yy < 0 || yy >= Hh) continue;
                #pragma unroll
                for (int dx = -1; dx <= 1; dx++) {
                    int xx = x + dx;
                    if (xx >= 0 && xx < Ww && sm[yy * Ww + xx] != 0.0f) o = 0;
                }
            }
            okbits |= (unsigned)o << j; myc += o;
        }
    }
    int v = myc;
    #pragma unroll
    for (int off = 1; off < 32; off <<= 1) {
        int t = __shfl_up_sync(0xffffffffu, v, off);
        if (lane >= off) v += t;
    }
    if (lane == 31) wsum[warp] = v;
    __syncthreads();
    if (tid == 0) {
        int run = 0;
        #pragma unroll
        for (int w = 0; w < 18; w++) { run += wsum[w]; wsum[w] = run; }
    }
    __syncthreads();
    int excl = (v - myc) + (warp > 0 ? wsum[warp - 1] : 0);
    #pragma unroll
    for (int j = 0; j < 8; j++)
        if ((okbits >> j) & 1u) s_list[excl++] = tid * 8 + j;
    __syncthreads();
    int cnt = wsum[17];

    if (blockIdx.x == 0) {
        for (int t = tid; t < cnt; t += 576) g_list[b][t] = s_list[t];
        if (tid == 0) g_cnt[b] = cnt;
    }

    int c = tid / 9, pp = tid % 9;
    int ph = pp / 3, pw = pp % 3;
    for (int i = blockIdx.x; i < cnt; i += 64) {
        int l = s_list[i];
        int y = l >> 6, x = l & 63;
        int yy = y + ph - 1, xx = x + pw - 1;
        float v2 = 0.f;
        if (yy >= 0 && yy < Hh && xx >= 0 && xx < Ww)
            v2 = bgin[(b * NC + c) * Ls + yy * Ww + xx] * (1.f - sm[yy * Ww + xx]);
        v2 += EPSF;
        float ss = v2 * v2;
        #pragma unroll
        for (int o = 16; o > 0; o >>= 1) ss += __shfl_xor_sync(0xffffffffu, ss, o);
        if (lane == 0) wred[warp] = ss;
        __syncthreads();
        float tot = 0.f;
        #pragma unroll
        for (int w = 0; w < 18; w++) tot += wred[w];
        g_K[b][i][tid] = v2 / sqrtf(tot);
        __syncthreads();
    }
}

// ---------------------------------------------------------------------------
// K2: corr — R8 compute body; staging loops division-hoisted (per-thread
// (r,j) fixed before the loop; identical stores). Grid (64 y, 4, Bz).
// ---------------------------------------------------------------------------
__global__ void __launch_bounds__(256) k_corr(const float* __restrict__ fgin) {
    int b = blockIdx.z;
    int cnt = g_cnt[b];
    int y  = blockIdx.x;
    int iq = blockIdx.y;
    int qq = (cnt + 3) >> 2;
    int ibeg = iq * qq, iend = min(ibeg + qq, cnt);
    if (ibeg >= iend) return;

    int tid = threadIdx.x;
    int cgi = tid >> 4;
    int xq  = tid & 15;
    int xbase = xq * 4;

    __shared__ float sfg[32][3][68];
    __shared__ float skc[CQ][KD];
    __shared__ float buf[16][193];

    // fixed per-thread staging coordinates (computed once)
    bool st_act = (tid < 204);                 // 3 rows x 68 cols per channel
    int  st_r = tid / 68, st_j = tid % 68;     // hoisted divisions
    int  st_gy = y - 1 + st_r;
    bool st_ok = st_act && (st_gy >= 0) && (st_gy < Hh) && (st_j >= 1) && (st_j <= 64);
    int  st_off = st_gy * Ww + (st_j - 1);     // safe: only used when st_ok

    for (int i0 = ibeg; i0 < iend; i0 += CQ) {
        int nch = min(CQ, iend - i0);
        float acc[CQ][4];
        #pragma unroll
        for (int j = 0; j < CQ; j++)
            #pragma unroll
            for (int xo = 0; xo < 4; xo++) acc[j][xo] = 0.f;

        for (int t = tid; t < nch * (KD / 4); t += 256) {
            int i = t / (KD / 4), k = t % (KD / 4);
            ((float4*)skc[i])[k] = ((const float4*)&g_K[b][i0 + i][0])[k];
        }

        for (int half = 0; half < 2; half++) {
            // staging: one predicated ld+st per channel, no division in loop
            const float* fgp = fgin + (b * NC + half * 32) * Ls;
            #pragma unroll 4
            for (int ch = 0; ch < 32; ch++) {
                if (st_act) {
                    float v = st_ok ? fgp[ch * Ls + st_off] : 0.f;
                    sfg[ch][st_r][st_j] = v;
                }
            }
            __syncthreads();

            #pragma unroll
            for (int c2 = 0; c2 < 2; c2++) {
                int ch = cgi * 2 + c2;
                int cglob = half * 32 + ch;
                float w[3][6];
                #pragma unroll
                for (int r = 0; r < 3; r++) {
                    float4 a = *(const float4*)&sfg[ch][r][xbase];
                    float2 e = *(const float2*)&sfg[ch][r][xbase + 4];
                    w[r][0] = a.x; w[r][1] = a.y; w[r][2] = a.z; w[r][3] = a.w;
                    w[r][4] = e.x; w[r][5] = e.y;
                }
                for (int j = 0; j < nch; j++) {
                    const float* kk = &skc[j][cglob * 9];
                    float k0 = kk[0], k1 = kk[1], k2 = kk[2];
                    float k3 = kk[3], k4 = kk[4], k5 = kk[5];
                    float k6 = kk[6], k7 = kk[7], k8 = kk[8];
                    #pragma unroll
                    for (int xo = 0; xo < 4; xo++) {
                        acc[j][xo] += k0 * w[0][xo] + k1 * w[0][xo + 1] + k2 * w[0][xo + 2]
                                    + k3 * w[1][xo] + k4 * w[1][xo + 1] + k5 * w[1][xo + 2]
                                    + k6 * w[2][xo] + k7 * w[2][xo + 1] + k8 * w[2][xo + 2];
                    }
                }
            }
            __syncthreads();
        }

        for (int j = 0; j < nch; j++)
            #pragma unroll
            for (int xo = 0; xo < 4; xo++)
                buf[cgi][j * 64 + xbase + xo] = acc[j][xo];
        __syncthreads();
        if (tid < nch * 64) {
            float s = 0.f;
            #pragma unroll
            for (int g = 0; g < 16; g++) s += buf[g][tid];
            int j = tid >> 6, x = tid & 63;
            g_corr[b][i0 + j][y * Ww + x] = s;
        }
        __syncthreads();
    }
}

// 3x3 spatial box-sum of a global corr row (zero outside grid) — slow path
__device__ __forceinline__ float boxsum_g(const float* __restrict__ row, int y, int x) {
    float a = 0.f;
    #pragma unroll
    for (int dy = -1; dy <= 1; dy++) {
        int yy = y + dy;
        if (yy < 0 || yy >= Hh) continue;
        const float* r = row + yy * Ww;
        #pragma unroll
        for (int dx = -1; dx <= 1; dx++) {
            int xx = x + dx;
            if (xx >= 0 && xx < Ww) a += r[xx];
        }
    }
    return a;
}

// ---------------------------------------------------------------------------
// K3: softmax/argmax/flow — proven R8 v2. Grid (64 y, Bz) x 256 threads.
// ---------------------------------------------------------------------------
__global__ void __launch_bounds__(256) k_soft(float* __restrict__ flowout) {
    int b = blockIdx.y, y = blockIdx.x;
    int cnt = g_cnt[b];
    int tid = threadIdx.x;
    int g = tid >> 6, x = tid & 63;
    int s = y * Ww + x;

    __shared__ float raw[MAXC][3][64];
    __shared__ float vsh[MAXC][64];
    __shared__ int   sl[MAXC];

    if (cnt <= MAXC) {
        for (int i = g; i < cnt; i += 4) {
            #pragma unroll
            for (int r = 0; r < 3; r++) {
                int gy = y - 1 + r;
                raw[i][r][x] = (gy >= 0 && gy < Hh) ? g_corr[b][i][gy * Ww + x] : 0.f;
            }
        }
        if (tid < cnt) sl[tid] = g_list[b][tid];
        __syncthreads();

        for (int i = g; i < cnt; i += 4) {
            float a = 0.f;
            #pragma unroll
            for (int r = 0; r < 3; r++) {
                #pragma unroll
                for (int dx = -1; dx <= 1; dx++) {
                    int xx = x + dx;
                    if (xx >= 0 && xx < 64) a += raw[i][r][xx];
                }
            }
            vsh[i][x] = 10.f * a;
        }
        __syncthreads();

        float vmax = (cnt < Ls) ? 0.f : -INFINITY;
        for (int i = 0; i < cnt; i++) vmax = fmaxf(vmax, vsh[i][x]);
        float denom = (cnt < Ls) ? (float)(Ls - cnt) * expf(-vmax) : 0.f;
        float bestv = -INFINITY; int bestl = 0;
        for (int i = 0; i < cnt; i++) {
            float vv = vsh[i][x];
            denom += expf(vv - vmax);
            if (vv > bestv) { bestv = vv; bestl = sl[i]; }   // ascending -> first max
        }
        float inv = 1.f / denom;
        for (int i = g; i < cnt; i += 4)
            g_sc[b][i][s] = expf(vsh[i][x] - vmax) * inv;

        if (g == 0) {
            flowout[(b * 2 + 0) * Ls + s] = (float)(bestl >> 6) - (float)y;
            flowout[(b * 2 + 1) * Ls + s] = (float)(bestl & 63) - (float)x;
        }
    } else if (g == 0) {
        float vmax = (cnt < Ls) ? 0.f : -INFINITY;
        for (int i = 0; i < cnt; i++) {
            float vv = 10.f * boxsum_g(&g_corr[b][i][0], y, x);
            vmax = fmaxf(vmax, vv);
            g_sc[b][i][s] = vv;
        }
        float denom = (cnt < Ls) ? (float)(Ls - cnt) * expf(-vmax) : 0.f;
        float bestv = -INFINITY; int bestl = 0;
        for (int i = 0; i < cnt; i++) {
            float vv = g_sc[b][i][s];
            float e = expf(vv - vmax);
            denom += e;
            if (vv > bestv) { bestv = vv; bestl = g_list[b][i]; }
            g_sc[b][i][s] = e;
        }
        float inv = 1.f / denom;
        for (int i = 0; i < cnt; i++) g_sc[b][i][s] *= inv;
        flowout[(b * 2 + 0) * Ls + s] = (float)(bestl >> 6) - (float)y;
        flowout[(b * 2 + 1) * Ls + s] = (float)(bestl & 63) - (float)x;
    }
}

// ---------------------------------------------------------------------------
// K4: rec — R8 compute body; ssc staging division-hoisted. Grid (64,4,Bz).
// ---------------------------------------------------------------------------
__global__ void __launch_bounds__(256) k_rec(const float* __restrict__ fgin,
                                             const float* __restrict__ mask,
                                             float* __restrict__ att) {
    int b = blockIdx.z, cg = blockIdx.y, y = blockIdx.x;
    int cnt = g_cnt[b];
    int tid = threadIdx.x;
    int c16 = tid >> 4, xg = tid & 15;
    int c = cg * 16 + c16;
    int xbase = xg * 4;

    __shared__ __align__(16) float sk[RCH][16 * 9];
    __shared__ float ssc[RCH][3][72];
    __shared__ float smask[64];

    if (tid < 64) smask[tid] = mask[b * Ls + y * Ww + tid];

    // fixed per-thread staging coordinates for ssc (3 x 72 = 216 entries)
    bool st_act = (tid < 216);
    int  st_r = tid / 72, st_j = tid % 72;     // hoisted divisions
    int  st_gy = y - 1 + st_r;
    bool st_ok = st_act && (st_gy >= 0) && (st_gy < Hh) && (st_j >= 1) && (st_j <= 64);
    int  st_off = st_gy * Ww + (st_j - 1);
    __syncthreads();

    float acc[4] = {0.f, 0.f, 0.f, 0.f};

    for (int c0 = 0; c0 < cnt; c0 += RCH) {
        int nchunk = min(RCH, cnt - c0);
        // sk staging as float4 copies (src offset cg*144 floats = 576B aligned)
        for (int t = tid; t < nchunk * 36; t += 256) {
            int i = t / 36, k = t % 36;
            ((float4*)sk[i])[k] = ((const float4*)&g_K[b][c0 + i][cg * 144])[k];
        }
        // ssc staging: one predicated ld+st per candidate, no division in loop
        if (st_act) {
            for (int i = 0; i < nchunk; i++) {
                float v = st_ok ? g_sc[b][c0 + i][st_off] : 0.f;
                ssc[i][st_r][st_j] = v;
            }
        }
        __syncthreads();

        for (int i = 0; i < nchunk; i++) {
            float ki[9];
            #pragma unroll
            for (int p = 0; p < 9; p++) ki[p] = sk[i][c16 * 9 + p];
            #pragma unroll
            for (int ph = 0; ph < 3; ph++) {
                const float* row = ssc[i][2 - ph];
                float4 a = *(const float4*)&row[xbase];
                float2 e = *(const float2*)&row[xbase + 4];
                float w0 = a.x, w1 = a.y, w2 = a.z, w3 = a.w, w4 = e.x, w5 = e.y;
                acc[0] += ki[ph * 3 + 0] * w2 + ki[ph * 3 + 1] * w1 + ki[ph * 3 + 2] * w0;
                acc[1] += ki[ph * 3 + 0] * w3 + ki[ph * 3 + 1] * w2 + ki[ph * 3 + 2] * w1;
                acc[2] += ki[ph * 3 + 0] * w4 + ki[ph * 3 + 1] * w3 + ki[ph * 3 + 2] * w2;
                acc[3] += ki[ph * 3 + 0] * w5 + ki[ph * 3 + 1] * w4 + ki[ph * 3 + 2] * w3;
            }
        }
        __syncthreads();
    }

    const float* fgrow = fgin + (b * NC + c) * Ls + y * Ww + xbase;
    float4 fgv = *(const float4*)fgrow;
    float4 o;
    {
        float m0 = smask[xbase + 0], m1 = smask[xbase + 1];
        float m2 = smask[xbase + 2], m3 = smask[xbase + 3];
        o.x = ((acc[0] * m0) / 9.f) * m0 + fgv.x * (1.f - m0);
        o.y = ((acc[1] * m1) / 9.f) * m1 + fgv.y * (1.f - m1);
        o.z = ((acc[2] * m2) / 9.f) * m2 + fgv.z * (1.f - m2);
        o.w = ((acc[3] * m3) / 9.f) * m3 + fgv.w * (1.f - m3);
    }
    *(float4*)(att + (b * NC + c) * Ls + y * Ww + xbase) = o;
}

// ---------------------------------------------------------------------------
extern "C" void kernel_launch(void* const* d_in, const int* in_sizes, int n_in,
                              void* d_out, int out_size) {
    const float* fg   = (const float*)d_in[0];   // foreground [2,64,64,64]
    const float* bg   = (const float*)d_in[1];   // background [2,64,64,64]
    const float* mask = (const float*)d_in[2];   // mask       [2,1,64,64]
    float* att  = (float*)d_out;                 // attended   [2,64,64,64]
    float* flow = (float*)d_out + Bz * NC * Ls;  // flow       [2,2,64,64]

    k_build<<<dim3(64, Bz), 576>>>(bg, mask);
    k_corr<<<dim3(64, 4, Bz), 256>>>(fg);
    k_soft<<<dim3(64, Bz), 256>>>(flow);
    k_rec<<<dim3(64, 4, Bz), 256>>>(fg, mask, att);
}